// round 13
// baseline (speedup 1.0000x reference)
#include <cuda_runtime.h>
#include <cstdint>

#define T_DIM 1024
#define B_DIM 32
#define D_DIM 512
#define C_DIM 1024
#define BLANK 0

// Output packing (floats): [out (T*B*D)] [out_padding (B*T)] [gloss (B*T)] [new_len (B)]
#define OFF_PAD   ((size_t)T_DIM * B_DIM * D_DIM)
#define OFF_GLOSS (OFF_PAD + (size_t)B_DIM * T_DIM)
#define OFF_LEN   (OFF_GLOSS + (size_t)B_DIM * T_DIM)

// Ticket layout: [0, 4096) argmax tickets (batch-grouped: b = tk>>7, 8 rows each)
//                [4096, 5120) gather tickets (batch-major: b = (tk-4096)>>5)
#define N_ARG_TICKETS  (B_DIM * T_DIM / 8)          // 4096
#define N_ALL_TICKETS  (N_ARG_TICKETS + B_DIM * 32) // 5120

// Scratch (device globals; no allocations allowed)
__device__ int g_pred[B_DIM * T_DIM];   // pred per (b,t), blank-forced by padding
__device__ int g_sync[B_DIM + 1];       // [0..31] per-batch done-row counters, [32] ticket

// ---------------------------------------------------------------------------
// Persistent fused kernel: argmax producer + RLE/gather consumer pipeline.
// ---------------------------------------------------------------------------
__global__ void __launch_bounds__(256)
fused_all(const float* __restrict__ rep, const float* __restrict__ logit,
          const unsigned char* __restrict__ padding, float* __restrict__ out) {
    int tid = threadIdx.x;         // 0..255
    int lane = tid & 31;
    int w = tid >> 5;              // warp 0..7

    __shared__ int s_cp[T_DIM];        // compacted predictions
    __shared__ int s_ct[T_DIM];        // compacted original frame index
    __shared__ int s_rs[T_DIM + 1];    // run starts; s_rs[len] = nb_total
    __shared__ int s_w[8];             // s_w[7] = nb_total (persists per batch)
    __shared__ int s_w2[8];            // s_w2[7] = new_len (persists per batch)
    __shared__ int s_ticket;

    int prev_b = -1;                   // batch whose RLE currently lives in smem
    float4 z = make_float4(0.f, 0.f, 0.f, 0.f);

    for (;;) {
        if (tid == 0) s_ticket = atomicAdd(&g_sync[B_DIM], 1);
        __syncthreads();
        int tk = s_ticket;
        if (tk >= N_ALL_TICKETS) break;

        if (tk < N_ARG_TICKETS) {
            // ---------------- argmax ticket: batch b, rows t0..t0+7 ----------
            int b = tk >> 7;
            int t = ((tk & 127) << 3) + w;          // warp w -> row t
            const float4* row =
                reinterpret_cast<const float4*>(logit + ((size_t)t * B_DIM + b) * C_DIM);

            float4 v[8];
            #pragma unroll
            for (int k = 0; k < 8; k++) v[k] = __ldcs(row + lane + 32 * k);

            float best = -3.402823466e+38f;
            int bi = 0;
            #pragma unroll
            for (int k = 0; k < 8; k++) {
                int base = (lane + 32 * k) * 4;
                float m01 = v[k].x; int i01 = base;
                if (v[k].y > m01) { m01 = v[k].y; i01 = base + 1; }
                float m23 = v[k].z; int i23 = base + 2;
                if (v[k].w > m23) { m23 = v[k].w; i23 = base + 3; }
                float mq = m01; int iq = i01;
                if (m23 > mq) { mq = m23; iq = i23; }
                if (mq > best) { best = mq; bi = iq; }
            }
            #pragma unroll
            for (int off = 16; off; off >>= 1) {
                float ov = __shfl_down_sync(0xFFFFFFFFu, best, off);
                int   oi = __shfl_down_sync(0xFFFFFFFFu, bi, off);
                if (ov > best || (ov == best && oi < bi)) { best = ov; bi = oi; }
            }
            if (lane == 0) {
                g_pred[b * T_DIM + t] = padding[b * T_DIM + t] ? BLANK : bi;
                __threadfence();                   // release g_pred store
                atomicAdd(&g_sync[b], 1);          // row done
            }
            continue;
        }

        // ---------------- gather ticket: batch b, chunk x ---------------------
        int g2 = tk - N_ARG_TICKETS;
        int b = g2 >> 5;
        int x = g2 & 31;                            // 0..31 (old blockIdx.x)

        if (b != prev_b) {
            // Wait for batch b's argmax to complete, then build RLE in smem.
            reinterpret_cast<int4*>(s_cp)[tid] = make_int4(-1, -1, -1, -1);
            if (tid == 0) {
                while (atomicAdd(&g_sync[b], 0) < T_DIM) __nanosleep(128);
                __threadfence();                   // acquire
            }
            __syncthreads();                        // s_cp init + g_pred visible

            // phase 1: compaction scan
            int4 p4 = reinterpret_cast<const int4*>(g_pred + b * T_DIM)[tid];
            int m0 = p4.x != BLANK, m1 = p4.y != BLANK,
                m2 = p4.z != BLANK, m3 = p4.w != BLANK;
            int local = m0 + m1 + m2 + m3;
            int v = local;
            #pragma unroll
            for (int o = 1; o < 32; o <<= 1) {
                int xx = __shfl_up_sync(0xFFFFFFFFu, v, o);
                if (lane >= o) v += xx;
            }
            if (lane == 31) s_w[w] = v;
            __syncthreads();
            if (tid == 0) {
                int run = 0;
                #pragma unroll
                for (int j = 0; j < 8; j++) { run += s_w[j]; s_w[j] = run; }
            }
            __syncthreads();
            int base = (w ? s_w[w - 1] : 0) + (v - local);
            int d = base;
            if (m0) { s_cp[d] = p4.x; s_ct[d] = 4 * tid;     d++; }
            if (m1) { s_cp[d] = p4.y; s_ct[d] = 4 * tid + 1; d++; }
            if (m2) { s_cp[d] = p4.z; s_ct[d] = 4 * tid + 2; d++; }
            if (m3) { s_cp[d] = p4.w; s_ct[d] = 4 * tid + 3; d++; }
            __syncthreads();

            // phase 2: run-start scan
            int i0 = 4 * tid;
            int c0 = s_cp[i0], c1 = s_cp[i0 + 1], c2 = s_cp[i0 + 2], c3 = s_cp[i0 + 3];
            int pm1 = (i0 == 0) ? -2 : s_cp[i0 - 1];
            int st0 = (c0 >= 0) && (c0 != pm1);
            int st1 = (c1 >= 0) && (c1 != c0);
            int st2 = (c2 >= 0) && (c2 != c1);
            int st3 = (c3 >= 0) && (c3 != c2);
            int local2 = st0 + st1 + st2 + st3;
            int v2 = local2;
            #pragma unroll
            for (int o = 1; o < 32; o <<= 1) {
                int xx = __shfl_up_sync(0xFFFFFFFFu, v2, o);
                if (lane >= o) v2 += xx;
            }
            if (lane == 31) s_w2[w] = v2;
            __syncthreads();
            if (tid == 0) {
                int run = 0;
                #pragma unroll
                for (int j = 0; j < 8; j++) { run += s_w2[j]; s_w2[j] = run; }
            }
            __syncthreads();
            int base2 = (w ? s_w2[w - 1] : 0) + (v2 - local2);
            int d2 = base2;
            if (st0) s_rs[d2++] = i0;
            if (st1) s_rs[d2++] = i0 + 1;
            if (st2) s_rs[d2++] = i0 + 2;
            if (st3) s_rs[d2++] = i0 + 3;
            if (tid == 0) s_rs[s_w2[7]] = s_w[7];   // s_rs[new_len] = nb_total
            __syncthreads();
            prev_b = b;
        }

        int new_len = s_w2[7];

        // small outputs (one ticket per batch)
        if (x == 0) {
            #pragma unroll
            for (int j = 0; j < 4; j++) {
                int n = tid + 256 * j;
                float gloss = -1.0f;
                if (n < new_len) gloss = (float)s_cp[s_rs[n]];
                out[OFF_GLOSS + (size_t)b * T_DIM + n] = gloss;
                out[OFF_PAD   + (size_t)b * T_DIM + n] = (n >= new_len) ? 1.0f : 0.0f;
            }
            if (tid == 0) out[OFF_LEN + b] = (float)new_len;
        }

        // gather/average: warp handles 4 rows (two pairs)
        int nb0 = x * 8 + w;               // 0..255
        #pragma unroll
        for (int p = 0; p < 2; p++) {
            int n0 = nb0 + 512 * p;
            int n1 = n0 + 256;

            float4* o0 = reinterpret_cast<float4*>(out + ((size_t)n0 * B_DIM + b) * D_DIM);
            float4* o1 = reinterpret_cast<float4*>(out + ((size_t)n1 * B_DIM + b) * D_DIM);

            bool v0ok = n0 < new_len;
            bool v1ok = n1 < new_len;
            int rs0 = 0, cc0 = 1, rs1 = 0, cc1 = 1;
            if (v0ok) { rs0 = s_rs[n0]; cc0 = s_rs[n0 + 1] - rs0; }
            if (v1ok) { rs1 = s_rs[n1]; cc1 = s_rs[n1 + 1] - rs1; }

            if ((!v0ok || cc0 == 1) && (!v1ok || cc1 == 1)) {
                const float4* r0 = nullptr;
                const float4* r1 = nullptr;
                if (v0ok) {
                    int t0 = s_ct[rs0];
                    r0 = reinterpret_cast<const float4*>(rep + ((size_t)t0 * B_DIM + b) * D_DIM);
                }
                if (v1ok) {
                    int t1 = s_ct[rs1];
                    r1 = reinterpret_cast<const float4*>(rep + ((size_t)t1 * B_DIM + b) * D_DIM);
                }
                float4 a0 = z, a1 = z, a2 = z, a3 = z;
                float4 b0 = z, b1 = z, b2 = z, b3 = z;
                if (v0ok) {
                    a0 = __ldcs(r0 + lane);      a1 = __ldcs(r0 + lane + 32);
                    a2 = __ldcs(r0 + lane + 64); a3 = __ldcs(r0 + lane + 96);
                }
                if (v1ok) {
                    b0 = __ldcs(r1 + lane);      b1 = __ldcs(r1 + lane + 32);
                    b2 = __ldcs(r1 + lane + 64); b3 = __ldcs(r1 + lane + 96);
                }
                __stcs(o0 + lane, a0);      __stcs(o0 + lane + 32, a1);
                __stcs(o0 + lane + 64, a2); __stcs(o0 + lane + 96, a3);
                __stcs(o1 + lane, b0);      __stcs(o1 + lane + 32, b1);
                __stcs(o1 + lane + 64, b2); __stcs(o1 + lane + 96, b3);
                continue;
            }

            #pragma unroll
            for (int r = 0; r < 2; r++) {
                bool valid = r ? v1ok : v0ok;
                int rs = r ? rs1 : rs0;
                int cnt = r ? cc1 : cc0;
                float4* orow = r ? o1 : o0;
                if (!valid) {
                    __stcs(orow + lane, z);      __stcs(orow + lane + 32, z);
                    __stcs(orow + lane + 64, z); __stcs(orow + lane + 96, z);
                    continue;
                }
                float4 acc0 = z, acc1 = z, acc2 = z, acc3 = z;
                for (int k = 0; k < cnt; k++) {
                    int t = s_ct[rs + k];
                    const float4* rrow =
                        reinterpret_cast<const float4*>(rep + ((size_t)t * B_DIM + b) * D_DIM);
                    float4 q0 = __ldcs(rrow + lane);
                    float4 q1 = __ldcs(rrow + lane + 32);
                    float4 q2 = __ldcs(rrow + lane + 64);
                    float4 q3 = __ldcs(rrow + lane + 96);
                    acc0.x += q0.x; acc0.y += q0.y; acc0.z += q0.z; acc0.w += q0.w;
                    acc1.x += q1.x; acc1.y += q1.y; acc1.z += q1.z; acc1.w += q1.w;
                    acc2.x += q2.x; acc2.y += q2.y; acc2.z += q2.z; acc2.w += q2.w;
                    acc3.x += q3.x; acc3.y += q3.y; acc3.z += q3.z; acc3.w += q3.w;
                }
                float inv = 1.0f / (float)cnt;
                acc0.x *= inv; acc0.y *= inv; acc0.z *= inv; acc0.w *= inv;
                acc1.x *= inv; acc1.y *= inv; acc1.z *= inv; acc1.w *= inv;
                acc2.x *= inv; acc2.y *= inv; acc2.z *= inv; acc2.w *= inv;
                acc3.x *= inv; acc3.y *= inv; acc3.z *= inv; acc3.w *= inv;
                __stcs(orow + lane, acc0);      __stcs(orow + lane + 32, acc1);
                __stcs(orow + lane + 64, acc2); __stcs(orow + lane + 96, acc3);
            }
        }
    }
}

extern "C" void kernel_launch(void* const* d_in, const int* in_sizes, int n_in,
                              void* d_out, int out_size) {
    const float* rep = (const float*)d_in[0];          // [T,B,D] f32
    const float* logit = (const float*)d_in[1];        // [T,B,C] f32
    const unsigned char* padding = (const unsigned char*)d_in[2];  // [B,T] bool
    float* out = (float*)d_out;

    // Reset ticket + per-batch done counters (graph-capturable memset node).
    void* sync_addr = nullptr;
    cudaGetSymbolAddress(&sync_addr, g_sync);
    cudaMemsetAsync(sync_addr, 0, (B_DIM + 1) * sizeof(int), 0);

    // One persistent kernel: 512 blocks x 256 threads, dynamic tickets.
    fused_all<<<512, 256>>>(rep, logit, padding, out);
}

// round 14
// speedup vs baseline: 1.0109x; 1.0109x over previous
#include <cuda_runtime.h>
#include <cstdint>

#define T_DIM 1024
#define B_DIM 32
#define D_DIM 512
#define C_DIM 1024
#define BLANK 0

// Output packing (floats): [out (T*B*D)] [out_padding (B*T)] [gloss (B*T)] [new_len (B)]
#define OFF_PAD   ((size_t)T_DIM * B_DIM * D_DIM)
#define OFF_GLOSS (OFF_PAD + (size_t)B_DIM * T_DIM)
#define OFF_LEN   (OFF_GLOSS + (size_t)B_DIM * T_DIM)

// Scratch (device globals; no allocations allowed)
__device__ int g_pred[B_DIM * T_DIM];   // pred per (b,t), blank-forced by padding
__device__ int g_done[B_DIM];           // per-batch completed-row counters

// ---------------------------------------------------------------------------
// K1: argmax over C per (t,b) row. Warp per row, BATCH-MAJOR block order so
// batches complete progressively. Per-row completion bumps g_done[b].
// PDL trigger at entry: K23 blocks may launch into freed slots immediately;
// correctness is carried by the g_done counters, not the trigger.
// ---------------------------------------------------------------------------
__global__ void argmax_kernel(const float* __restrict__ logit,
                              const unsigned char* __restrict__ padding) {
    cudaTriggerProgrammaticLaunchCompletion();

    int gw = (blockIdx.x * blockDim.x + threadIdx.x) >> 5;  // 0..32767
    int lane = threadIdx.x & 31;
    int b = gw >> 10;              // batch-major: blocks 0..127 -> batch 0, ...
    int t = gw & 1023;

    const float4* row =
        reinterpret_cast<const float4*>(logit + ((size_t)t * B_DIM + b) * C_DIM);

    float4 v[8];
    #pragma unroll
    for (int k = 0; k < 8; k++) v[k] = __ldcs(row + lane + 32 * k);

    // Lowest index wins on ties (strictly-greater replaces, ascending order).
    float best = -3.402823466e+38f;
    int bi = 0;
    #pragma unroll
    for (int k = 0; k < 8; k++) {
        int base = (lane + 32 * k) * 4;
        float m01 = v[k].x; int i01 = base;
        if (v[k].y > m01) { m01 = v[k].y; i01 = base + 1; }
        float m23 = v[k].z; int i23 = base + 2;
        if (v[k].w > m23) { m23 = v[k].w; i23 = base + 3; }
        float mq = m01; int iq = i01;
        if (m23 > mq) { mq = m23; iq = i23; }
        if (mq > best) { best = mq; bi = iq; }
    }
    #pragma unroll
    for (int off = 16; off; off >>= 1) {
        float ov = __shfl_down_sync(0xFFFFFFFFu, best, off);
        int   oi = __shfl_down_sync(0xFFFFFFFFu, bi, off);
        if (ov > best || (ov == best && oi < bi)) { best = ov; bi = oi; }
    }
    if (lane == 0) {
        g_pred[b * T_DIM + t] = padding[b * T_DIM + t] ? BLANK : bi;
        __threadfence();               // release the g_pred store
        atomicAdd(&g_done[b], 1);      // row complete
    }
}

// ---------------------------------------------------------------------------
// K23: fused RLE + gather/average. Grid (32, B); launch order serves batch 0
// first. Each block spin-waits on its OWN batch's counter -> early batches
// start while K1 is still draining later ones.
// ---------------------------------------------------------------------------
__global__ void __launch_bounds__(256)
fused_rle_gather(const float* __restrict__ rep, float* __restrict__ out) {
    int b = blockIdx.y;
    int tid = threadIdx.x;         // 0..255
    int lane = tid & 31;
    int w = tid >> 5;              // warp 0..7

    __shared__ int s_cp[T_DIM];        // compacted predictions
    __shared__ int s_ct[T_DIM];        // compacted original frame index
    __shared__ int s_rs[T_DIM + 1];    // run start (compacted idx); s_rs[len]=nb_total
    __shared__ int s_w[8];
    __shared__ int s_w2[8];

    // Prologue independent of K1.
    reinterpret_cast<int4*>(s_cp)[tid] = make_int4(-1, -1, -1, -1);

    // Wait for THIS batch's argmax rows only.
    if (tid == 0) {
        while (atomicAdd(&g_done[b], 0) < T_DIM) __nanosleep(256);
        __threadfence();               // acquire
    }
    __syncthreads();

    // ---- phase 1: load pred row, scan mask -> compaction ----
    int4 p4 = reinterpret_cast<const int4*>(g_pred + b * T_DIM)[tid];
    int m0 = p4.x != BLANK, m1 = p4.y != BLANK, m2 = p4.z != BLANK, m3 = p4.w != BLANK;
    int local = m0 + m1 + m2 + m3;

    int v = local;
    #pragma unroll
    for (int o = 1; o < 32; o <<= 1) {
        int x = __shfl_up_sync(0xFFFFFFFFu, v, o);
        if (lane >= o) v += x;
    }
    if (lane == 31) s_w[w] = v;
    __syncthreads();
    if (tid == 0) {
        int run = 0;
        #pragma unroll
        for (int j = 0; j < 8; j++) { run += s_w[j]; s_w[j] = run; }
    }
    __syncthreads();
    int base = (w ? s_w[w - 1] : 0) + (v - local);   // exclusive start
    int nb_total = s_w[7];

    int d = base;
    if (m0) { s_cp[d] = p4.x; s_ct[d] = 4 * tid;     d++; }
    if (m1) { s_cp[d] = p4.y; s_ct[d] = 4 * tid + 1; d++; }
    if (m2) { s_cp[d] = p4.z; s_ct[d] = 4 * tid + 2; d++; }
    if (m3) { s_cp[d] = p4.w; s_ct[d] = 4 * tid + 3; d++; }
    __syncthreads();

    // ---- phase 2: run-start scan on compacted stream ----
    int i0 = 4 * tid;
    int c0 = s_cp[i0], c1 = s_cp[i0 + 1], c2 = s_cp[i0 + 2], c3 = s_cp[i0 + 3];
    int pm1 = (i0 == 0) ? -2 : s_cp[i0 - 1];
    int st0 = (c0 >= 0) && (c0 != pm1);
    int st1 = (c1 >= 0) && (c1 != c0);
    int st2 = (c2 >= 0) && (c2 != c1);
    int st3 = (c3 >= 0) && (c3 != c2);
    int local2 = st0 + st1 + st2 + st3;

    int v2 = local2;
    #pragma unroll
    for (int o = 1; o < 32; o <<= 1) {
        int x = __shfl_up_sync(0xFFFFFFFFu, v2, o);
        if (lane >= o) v2 += x;
    }
    if (lane == 31) s_w2[w] = v2;
    __syncthreads();
    if (tid == 0) {
        int run = 0;
        #pragma unroll
        for (int j = 0; j < 8; j++) { run += s_w2[j]; s_w2[j] = run; }
    }
    __syncthreads();
    int base2 = (w ? s_w2[w - 1] : 0) + (v2 - local2);
    int new_len = s_w2[7];

    int d2 = base2;
    if (st0) s_rs[d2++] = i0;
    if (st1) s_rs[d2++] = i0 + 1;
    if (st2) s_rs[d2++] = i0 + 2;
    if (st3) s_rs[d2++] = i0 + 3;
    if (tid == 0) s_rs[new_len] = nb_total;
    __syncthreads();

    // ---- small outputs (one block column only) ----
    if (blockIdx.x == 0) {
        #pragma unroll
        for (int j = 0; j < 4; j++) {
            int n = tid + 256 * j;
            float gloss = -1.0f;
            if (n < new_len) gloss = (float)s_cp[s_rs[n]];
            out[OFF_GLOSS + (size_t)b * T_DIM + n] = gloss;
            out[OFF_PAD   + (size_t)b * T_DIM + n] = (n >= new_len) ? 1.0f : 0.0f;
        }
        if (tid == 0) out[OFF_LEN + b] = (float)new_len;
    }

    // ---- phase 3: gather/average. Warp handles 4 rows (two pairs) ----
    int nb0 = blockIdx.x * 8 + w;          // 0..255
    float4 z = make_float4(0.f, 0.f, 0.f, 0.f);

    #pragma unroll
    for (int p = 0; p < 2; p++) {
        int n0 = nb0 + 512 * p;            // p=0: 0..255 ; p=1: 512..767
        int n1 = n0 + 256;                 // p=0: 256..511; p=1: 768..1023

        float4* o0 = reinterpret_cast<float4*>(out + ((size_t)n0 * B_DIM + b) * D_DIM);
        float4* o1 = reinterpret_cast<float4*>(out + ((size_t)n1 * B_DIM + b) * D_DIM);

        bool v0ok = n0 < new_len;
        bool v1ok = n1 < new_len;
        int rs0 = 0, cc0 = 1, rs1 = 0, cc1 = 1;
        if (v0ok) { rs0 = s_rs[n0]; cc0 = s_rs[n0 + 1] - rs0; }
        if (v1ok) { rs1 = s_rs[n1]; cc1 = s_rs[n1 + 1] - rs1; }

        if ((!v0ok || cc0 == 1) && (!v1ok || cc1 == 1)) {
            // Fast path: each valid row is a pure copy of one rep row (MLP=8).
            const float4* r0 = nullptr;
            const float4* r1 = nullptr;
            if (v0ok) {
                int t0 = s_ct[rs0];
                r0 = reinterpret_cast<const float4*>(rep + ((size_t)t0 * B_DIM + b) * D_DIM);
            }
            if (v1ok) {
                int t1 = s_ct[rs1];
                r1 = reinterpret_cast<const float4*>(rep + ((size_t)t1 * B_DIM + b) * D_DIM);
            }
            float4 a0 = z, a1 = z, a2 = z, a3 = z;
            float4 b0 = z, b1 = z, b2 = z, b3 = z;
            if (v0ok) {
                a0 = __ldcs(r0 + lane);      a1 = __ldcs(r0 + lane + 32);
                a2 = __ldcs(r0 + lane + 64); a3 = __ldcs(r0 + lane + 96);
            }
            if (v1ok) {
                b0 = __ldcs(r1 + lane);      b1 = __ldcs(r1 + lane + 32);
                b2 = __ldcs(r1 + lane + 64); b3 = __ldcs(r1 + lane + 96);
            }
            __stcs(o0 + lane, a0);      __stcs(o0 + lane + 32, a1);
            __stcs(o0 + lane + 64, a2); __stcs(o0 + lane + 96, a3);
            __stcs(o1 + lane, b0);      __stcs(o1 + lane + 32, b1);
            __stcs(o1 + lane + 64, b2); __stcs(o1 + lane + 96, b3);
            continue;
        }

        // General path: per-row averaging loop.
        #pragma unroll
        for (int r = 0; r < 2; r++) {
            bool valid = r ? v1ok : v0ok;
            int rs = r ? rs1 : rs0;
            int cnt = r ? cc1 : cc0;
            float4* orow = r ? o1 : o0;
            if (!valid) {
                __stcs(orow + lane, z);      __stcs(orow + lane + 32, z);
                __stcs(orow + lane + 64, z); __stcs(orow + lane + 96, z);
                continue;
            }
            float4 acc0 = z, acc1 = z, acc2 = z, acc3 = z;
            for (int k = 0; k < cnt; k++) {
                int t = s_ct[rs + k];
                const float4* rrow =
                    reinterpret_cast<const float4*>(rep + ((size_t)t * B_DIM + b) * D_DIM);
                float4 q0 = __ldcs(rrow + lane);
                float4 q1 = __ldcs(rrow + lane + 32);
                float4 q2 = __ldcs(rrow + lane + 64);
                float4 q3 = __ldcs(rrow + lane + 96);
                acc0.x += q0.x; acc0.y += q0.y; acc0.z += q0.z; acc0.w += q0.w;
                acc1.x += q1.x; acc1.y += q1.y; acc1.z += q1.z; acc1.w += q1.w;
                acc2.x += q2.x; acc2.y += q2.y; acc2.z += q2.z; acc2.w += q2.w;
                acc3.x += q3.x; acc3.y += q3.y; acc3.z += q3.z; acc3.w += q3.w;
            }
            float inv = 1.0f / (float)cnt;
            acc0.x *= inv; acc0.y *= inv; acc0.z *= inv; acc0.w *= inv;
            acc1.x *= inv; acc1.y *= inv; acc1.z *= inv; acc1.w *= inv;
            acc2.x *= inv; acc2.y *= inv; acc2.z *= inv; acc2.w *= inv;
            acc3.x *= inv; acc3.y *= inv; acc3.z *= inv; acc3.w *= inv;
            __stcs(orow + lane, acc0);      __stcs(orow + lane + 32, acc1);
            __stcs(orow + lane + 64, acc2); __stcs(orow + lane + 96, acc3);
        }
    }
}

extern "C" void kernel_launch(void* const* d_in, const int* in_sizes, int n_in,
                              void* d_out, int out_size) {
    const float* rep = (const float*)d_in[0];          // [T,B,D] f32
    const float* logit = (const float*)d_in[1];        // [T,B,C] f32
    const unsigned char* padding = (const unsigned char*)d_in[2];  // [B,T] bool
    float* out = (float*)d_out;

    // Reset per-batch counters (graph-capturable memset node).
    void* done_addr = nullptr;
    cudaGetSymbolAddress(&done_addr, g_done);
    cudaMemsetAsync(done_addr, 0, B_DIM * sizeof(int), 0);

    // K1: 4096 blocks, batch-major row order, PDL trigger at entry.
    argmax_kernel<<<(T_DIM * B_DIM) / 8, 256>>>(logit, padding);

    // K23 with PDL: blocks launch into freed slots while K1 drains; each
    // block waits only on its own batch's counter.
    cudaLaunchConfig_t cfg = {};
    cfg.gridDim = dim3(T_DIM / 4 / 8, B_DIM);
    cfg.blockDim = dim3(256);
    cfg.dynamicSmemBytes = 0;
    cfg.stream = 0;
    cudaLaunchAttribute attr[1];
    attr[0].id = cudaLaunchAttributeProgrammaticStreamSerialization;
    attr[0].val.programmaticStreamSerializationAllowed = 1;
    cfg.attrs = attr;
    cfg.numAttrs = 1;
    cudaLaunchKernelEx(&cfg, fused_rle_gather, rep, out);
}

// round 15
// speedup vs baseline: 1.2614x; 1.2477x over previous
#include <cuda_runtime.h>
#include <cstdint>

#define T_DIM 1024
#define B_DIM 32
#define D_DIM 512
#define C_DIM 1024
#define BLANK 0

// Output packing (floats): [out (T*B*D)] [out_padding (B*T)] [gloss (B*T)] [new_len (B)]
#define OFF_PAD   ((size_t)T_DIM * B_DIM * D_DIM)
#define OFF_GLOSS (OFF_PAD + (size_t)B_DIM * T_DIM)
#define OFF_LEN   (OFF_GLOSS + (size_t)B_DIM * T_DIM)

// Scratch (device global; no allocations allowed)
__device__ int g_pred[B_DIM * T_DIM];   // pred per (b,t), blank-forced by padding

// ---------------------------------------------------------------------------
// K1: argmax over C per (t,b) row. Warp per row, 8 float4 batched into regs,
// quad-tree reduce, __ldcs streaming. Triggers PDL completion after store.
// ---------------------------------------------------------------------------
__global__ void argmax_kernel(const float* __restrict__ logit,
                              const unsigned char* __restrict__ padding) {
    int warp = (blockIdx.x * blockDim.x + threadIdx.x) >> 5;
    int lane = threadIdx.x & 31;
    if (warp >= T_DIM * B_DIM) return;
    int t = warp / B_DIM;
    int b = warp % B_DIM;

    const float4* row = reinterpret_cast<const float4*>(logit + (size_t)warp * C_DIM);

    float4 v[8];
    #pragma unroll
    for (int k = 0; k < 8; k++) v[k] = __ldcs(row + lane + 32 * k);

    // Lowest index wins on ties (strictly-greater replaces, ascending order).
    float best = -3.402823466e+38f;
    int bi = 0;
    #pragma unroll
    for (int k = 0; k < 8; k++) {
        int base = (lane + 32 * k) * 4;
        float m01 = v[k].x; int i01 = base;
        if (v[k].y > m01) { m01 = v[k].y; i01 = base + 1; }
        float m23 = v[k].z; int i23 = base + 2;
        if (v[k].w > m23) { m23 = v[k].w; i23 = base + 3; }
        float mq = m01; int iq = i01;
        if (m23 > mq) { mq = m23; iq = i23; }
        if (mq > best) { best = mq; bi = iq; }
    }
    #pragma unroll
    for (int off = 16; off; off >>= 1) {
        float ov = __shfl_down_sync(0xFFFFFFFFu, best, off);
        int   oi = __shfl_down_sync(0xFFFFFFFFu, bi, off);
        if (ov > best || (ov == best && oi < bi)) { best = ov; bi = oi; }
    }
    if (lane == 0) {
        int p = padding[b * T_DIM + t] ? BLANK : bi;
        g_pred[b * T_DIM + t] = p;
    }
    cudaTriggerProgrammaticLaunchCompletion();
}

// ---------------------------------------------------------------------------
// K23: fused RLE + gather/average. Grid (32, B). PDL: launched while K1
// drains; syncs on grid dependency right before the first g_pred read.
// ---------------------------------------------------------------------------
__global__ void __launch_bounds__(256)
fused_rle_gather(const float* __restrict__ rep, float* __restrict__ out) {
    int b = blockIdx.y;
    int tid = threadIdx.x;         // 0..255
    int lane = tid & 31;
    int w = tid >> 5;              // warp 0..7

    __shared__ int s_cp[T_DIM];        // compacted predictions
    __shared__ int s_ct[T_DIM];        // compacted original frame index
    __shared__ int s_rs[T_DIM + 1];    // run start (compacted idx); s_rs[len]=nb_total
    __shared__ int s_w[8];
    __shared__ int s_w2[8];

    // Prologue that doesn't depend on K1: init compacted stream.
    reinterpret_cast<int4*>(s_cp)[tid] = make_int4(-1, -1, -1, -1);

    // Wait for K1's writes to be visible.
    cudaGridDependencySynchronize();

    // ---- phase 1: load pred row, scan mask -> compaction ----
    int4 p4 = reinterpret_cast<const int4*>(g_pred + b * T_DIM)[tid];
    int m0 = p4.x != BLANK, m1 = p4.y != BLANK, m2 = p4.z != BLANK, m3 = p4.w != BLANK;
    int local = m0 + m1 + m2 + m3;

    int v = local;
    #pragma unroll
    for (int o = 1; o < 32; o <<= 1) {
        int x = __shfl_up_sync(0xFFFFFFFFu, v, o);
        if (lane >= o) v += x;
    }
    if (lane == 31) s_w[w] = v;
    __syncthreads();
    if (tid == 0) {
        int run = 0;
        #pragma unroll
        for (int j = 0; j < 8; j++) { run += s_w[j]; s_w[j] = run; }
    }
    __syncthreads();
    int base = (w ? s_w[w - 1] : 0) + (v - local);   // exclusive start
    int nb_total = s_w[7];

    int d = base;
    if (m0) { s_cp[d] = p4.x; s_ct[d] = 4 * tid;     d++; }
    if (m1) { s_cp[d] = p4.y; s_ct[d] = 4 * tid + 1; d++; }
    if (m2) { s_cp[d] = p4.z; s_ct[d] = 4 * tid + 2; d++; }
    if (m3) { s_cp[d] = p4.w; s_ct[d] = 4 * tid + 3; d++; }
    __syncthreads();

    // ---- phase 2: run-start scan on compacted stream ----
    int i0 = 4 * tid;
    int c0 = s_cp[i0], c1 = s_cp[i0 + 1], c2 = s_cp[i0 + 2], c3 = s_cp[i0 + 3];
    int pm1 = (i0 == 0) ? -2 : s_cp[i0 - 1];
    int st0 = (c0 >= 0) && (c0 != pm1);
    int st1 = (c1 >= 0) && (c1 != c0);
    int st2 = (c2 >= 0) && (c2 != c1);
    int st3 = (c3 >= 0) && (c3 != c2);
    int local2 = st0 + st1 + st2 + st3;

    int v2 = local2;
    #pragma unroll
    for (int o = 1; o < 32; o <<= 1) {
        int x = __shfl_up_sync(0xFFFFFFFFu, v2, o);
        if (lane >= o) v2 += x;
    }
    if (lane == 31) s_w2[w] = v2;
    __syncthreads();
    if (tid == 0) {
        int run = 0;
        #pragma unroll
        for (int j = 0; j < 8; j++) { run += s_w2[j]; s_w2[j] = run; }
    }
    __syncthreads();
    int base2 = (w ? s_w2[w - 1] : 0) + (v2 - local2);
    int new_len = s_w2[7];

    int d2 = base2;
    if (st0) s_rs[d2++] = i0;
    if (st1) s_rs[d2++] = i0 + 1;
    if (st2) s_rs[d2++] = i0 + 2;
    if (st3) s_rs[d2++] = i0 + 3;
    if (tid == 0) s_rs[new_len] = nb_total;
    __syncthreads();

    // ---- small outputs (one block column only) ----
    if (blockIdx.x == 0) {
        #pragma unroll
        for (int j = 0; j < 4; j++) {
            int n = tid + 256 * j;
            float gloss = -1.0f;
            if (n < new_len) gloss = (float)s_cp[s_rs[n]];
            out[OFF_GLOSS + (size_t)b * T_DIM + n] = gloss;
            out[OFF_PAD   + (size_t)b * T_DIM + n] = (n >= new_len) ? 1.0f : 0.0f;
        }
        if (tid == 0) out[OFF_LEN + b] = (float)new_len;
    }

    // ---- phase 3: gather/average. Warp handles 4 rows (two pairs) ----
    int nb0 = blockIdx.x * 8 + w;          // 0..255
    float4 z = make_float4(0.f, 0.f, 0.f, 0.f);

    #pragma unroll
    for (int p = 0; p < 2; p++) {
        int n0 = nb0 + 512 * p;            // p=0: 0..255 ; p=1: 512..767
        int n1 = n0 + 256;                 // p=0: 256..511; p=1: 768..1023

        float4* o0 = reinterpret_cast<float4*>(out + ((size_t)n0 * B_DIM + b) * D_DIM);
        float4* o1 = reinterpret_cast<float4*>(out + ((size_t)n1 * B_DIM + b) * D_DIM);

        bool v0ok = n0 < new_len;
        bool v1ok = n1 < new_len;
        int rs0 = 0, cc0 = 1, rs1 = 0, cc1 = 1;
        if (v0ok) { rs0 = s_rs[n0]; cc0 = s_rs[n0 + 1] - rs0; }
        if (v1ok) { rs1 = s_rs[n1]; cc1 = s_rs[n1 + 1] - rs1; }

        if ((!v0ok || cc0 == 1) && (!v1ok || cc1 == 1)) {
            // Fast path: each valid row is a pure copy of one rep row (MLP=8).
            const float4* r0 = nullptr;
            const float4* r1 = nullptr;
            if (v0ok) {
                int t0 = s_ct[rs0];
                r0 = reinterpret_cast<const float4*>(rep + ((size_t)t0 * B_DIM + b) * D_DIM);
            }
            if (v1ok) {
                int t1 = s_ct[rs1];
                r1 = reinterpret_cast<const float4*>(rep + ((size_t)t1 * B_DIM + b) * D_DIM);
            }
            float4 a0 = z, a1 = z, a2 = z, a3 = z;
            float4 b0 = z, b1 = z, b2 = z, b3 = z;
            if (v0ok) {
                a0 = __ldcs(r0 + lane);      a1 = __ldcs(r0 + lane + 32);
                a2 = __ldcs(r0 + lane + 64); a3 = __ldcs(r0 + lane + 96);
            }
            if (v1ok) {
                b0 = __ldcs(r1 + lane);      b1 = __ldcs(r1 + lane + 32);
                b2 = __ldcs(r1 + lane + 64); b3 = __ldcs(r1 + lane + 96);
            }
            __stcs(o0 + lane, a0);      __stcs(o0 + lane + 32, a1);
            __stcs(o0 + lane + 64, a2); __stcs(o0 + lane + 96, a3);
            __stcs(o1 + lane, b0);      __stcs(o1 + lane + 32, b1);
            __stcs(o1 + lane + 64, b2); __stcs(o1 + lane + 96, b3);
            continue;
        }

        // General path: per-row averaging loop.
        #pragma unroll
        for (int r = 0; r < 2; r++) {
            bool valid = r ? v1ok : v0ok;
            int rs = r ? rs1 : rs0;
            int cnt = r ? cc1 : cc0;
            float4* orow = r ? o1 : o0;
            if (!valid) {
                __stcs(orow + lane, z);      __stcs(orow + lane + 32, z);
                __stcs(orow + lane + 64, z); __stcs(orow + lane + 96, z);
                continue;
            }
            float4 acc0 = z, acc1 = z, acc2 = z, acc3 = z;
            for (int k = 0; k < cnt; k++) {
                int t = s_ct[rs + k];
                const float4* rrow =
                    reinterpret_cast<const float4*>(rep + ((size_t)t * B_DIM + b) * D_DIM);
                float4 q0 = __ldcs(rrow + lane);
                float4 q1 = __ldcs(rrow + lane + 32);
                float4 q2 = __ldcs(rrow + lane + 64);
                float4 q3 = __ldcs(rrow + lane + 96);
                acc0.x += q0.x; acc0.y += q0.y; acc0.z += q0.z; acc0.w += q0.w;
                acc1.x += q1.x; acc1.y += q1.y; acc1.z += q1.z; acc1.w += q1.w;
                acc2.x += q2.x; acc2.y += q2.y; acc2.z += q2.z; acc2.w += q2.w;
                acc3.x += q3.x; acc3.y += q3.y; acc3.z += q3.z; acc3.w += q3.w;
            }
            float inv = 1.0f / (float)cnt;
            acc0.x *= inv; acc0.y *= inv; acc0.z *= inv; acc0.w *= inv;
            acc1.x *= inv; acc1.y *= inv; acc1.z *= inv; acc1.w *= inv;
            acc2.x *= inv; acc2.y *= inv; acc2.z *= inv; acc2.w *= inv;
            acc3.x *= inv; acc3.y *= inv; acc3.z *= inv; acc3.w *= inv;
            __stcs(orow + lane, acc0);      __stcs(orow + lane + 32, acc1);
            __stcs(orow + lane + 64, acc2); __stcs(orow + lane + 96, acc3);
        }
    }
}

extern "C" void kernel_launch(void* const* d_in, const int* in_sizes, int n_in,
                              void* d_out, int out_size) {
    const float* rep = (const float*)d_in[0];          // [T,B,D] f32
    const float* logit = (const float*)d_in[1];        // [T,B,C] f32
    const unsigned char* padding = (const unsigned char*)d_in[2];  // [B,T] bool
    float* out = (float*)d_out;

    // K1: 32768 rows, warp per row, 8 rows per 256-thread block
    argmax_kernel<<<(T_DIM * B_DIM) / 8, 256>>>(logit, padding);

    // K23 with Programmatic Dependent Launch: overlap launch/fill with K1 drain.
    cudaLaunchConfig_t cfg = {};
    cfg.gridDim = dim3(T_DIM / 4 / 8, B_DIM);
    cfg.blockDim = dim3(256);
    cfg.dynamicSmemBytes = 0;
    cfg.stream = 0;  // legacy default stream (same one the harness captures)
    cudaLaunchAttribute attr[1];
    attr[0].id = cudaLaunchAttributeProgrammaticStreamSerialization;
    attr[0].val.programmaticStreamSerializationAllowed = 1;
    cfg.attrs = attr;
    cfg.numAttrs = 1;
    cudaLaunchKernelEx(&cfg, fused_rle_gather, rep, out);
}